// round 4
// baseline (speedup 1.0000x reference)
#include <cuda_runtime.h>
#include <math.h>

#define NV   100000
#define NE   10000
#define NP   1600000
#define CIN  256
#define CMID 128
#define COUT 64
#define NEG  0.2f

// ---------------- scratch (device globals; no allocation allowed) ----------
__device__ float g_h[NV * COUT];        // MLP output h
__device__ float g_efeat[NE * COUT];    // hyperedge mean feature
__device__ int   g_cnt_e[NE];           // hyperedge degree
__device__ int   g_cnt_v[NV];           // vertex incidence degree
__device__ int   g_cnt_g[NV];           // vertex graph in-degree
__device__ int   g_off_e[NE];
__device__ int   g_off_v[NV];
__device__ int   g_off_g[NV];
__device__ int   g_cur_e[NE];
__device__ int   g_cur_v[NV];
__device__ int   g_cur_g[NV];
__device__ int   g_csr_ev[NP];          // per-hyperedge: list of vertex ids
__device__ int   g_csr_ve[NP];          // per-vertex: list of hyperedge ids
__device__ int   g_csr_g[NP];           // per-vertex: list of src vertex ids

__device__ __forceinline__ float lrelu(float v) { return v > 0.f ? v : NEG * v; }

typedef unsigned long long u64;

__device__ __forceinline__ u64 fma2(u64 a, u64 b, u64 c) {
    u64 d;
    asm("fma.rn.f32x2 %0, %1, %2, %3;" : "=l"(d) : "l"(a), "l"(b), "l"(c));
    return d;
}
__device__ __forceinline__ float sum2(u64 p) {
    float lo, hi;
    asm("mov.b64 {%0,%1}, %2;" : "=f"(lo), "=f"(hi) : "l"(p));
    return lo + hi;
}

// ---------------- zero counters ---------------------------------------------
__global__ void zero_kernel() {
    int i = blockIdx.x * blockDim.x + threadIdx.x;
    if (i < NE) { g_cnt_e[i] = 0; g_cur_e[i] = 0; }
    if (i < NV) {
        g_cnt_v[i] = 0; g_cur_v[i] = 0;
        g_cnt_g[i] = 0; g_cur_g[i] = 0;
    }
}

// ---------------- histogram -------------------------------------------------
__global__ void count_kernel(const int* __restrict__ hg_v,
                             const int* __restrict__ hg_e,
                             const int* __restrict__ g_dst) {
    int i = blockIdx.x * blockDim.x + threadIdx.x;
    if (i >= NP) return;
    atomicAdd(&g_cnt_e[__ldg(hg_e + i)], 1);
    atomicAdd(&g_cnt_v[__ldg(hg_v + i)], 1);
    atomicAdd(&g_cnt_g[__ldg(g_dst + i)], 1);
}

// ---------------- 3 exclusive scans (one block each) ------------------------
#define SCAN_T 1024
__global__ void scan_kernel() {
    const int* cnt; int* off; int n;
    if (blockIdx.x == 0)      { cnt = g_cnt_e; off = g_off_e; n = NE; }
    else if (blockIdx.x == 1) { cnt = g_cnt_v; off = g_off_v; n = NV; }
    else                      { cnt = g_cnt_g; off = g_off_g; n = NV; }

    __shared__ int ssum[SCAN_T];
    int t = threadIdx.x;
    int chunk = (n + SCAN_T - 1) / SCAN_T;
    int lo = t * chunk, hi = min(n, lo + chunk);
    int s = 0;
    for (int i = lo; i < hi; i++) s += cnt[i];
    ssum[t] = s;
    __syncthreads();
    for (int d = 1; d < SCAN_T; d <<= 1) {
        int v = (t >= d) ? ssum[t - d] : 0;
        __syncthreads();
        ssum[t] += v;
        __syncthreads();
    }
    int excl = (t == 0) ? 0 : ssum[t - 1];
    for (int i = lo; i < hi; i++) { off[i] = excl; excl += cnt[i]; }
}

// ---------------- CSR fill --------------------------------------------------
__global__ void fill_kernel(const int* __restrict__ hg_v,
                            const int* __restrict__ hg_e,
                            const int* __restrict__ g_src,
                            const int* __restrict__ g_dst) {
    int i = blockIdx.x * blockDim.x + threadIdx.x;
    if (i >= NP) return;
    int e = __ldg(hg_e + i), v = __ldg(hg_v + i);
    g_csr_ev[g_off_e[e] + atomicAdd(&g_cur_e[e], 1)] = v;
    g_csr_ve[g_off_v[v] + atomicAdd(&g_cur_v[v], 1)] = e;
    int d = __ldg(g_dst + i);
    g_csr_g[g_off_g[d] + atomicAdd(&g_cur_g[d], 1)] = __ldg(g_src + i);
}

// ---------------- fused MLP: h = lrelu(x@W1+b1)@W2 + b2 --------------------
#define TILE_R 32
#define RPW    4
#define MLP_THREADS 256
#define S1 (CIN + 2)
#define S2 (CMID + 2)
#define SMEM_FLOATS (CMID*S1 + COUT*S2 + TILE_R*CIN + TILE_R*CMID + CMID + COUT)

__global__ __launch_bounds__(MLP_THREADS, 1)
void mlp_kernel(const float* __restrict__ x,
                const float* __restrict__ W1, const float* __restrict__ b1,
                const float* __restrict__ W2, const float* __restrict__ b2) {
    extern __shared__ float sm[];
    float* W1T  = sm;
    float* W2T  = W1T + CMID * S1;
    float* xs   = W2T + COUT * S2;
    float* mids = xs  + TILE_R * CIN;
    float* b1s  = mids + TILE_R * CMID;
    float* b2s  = b1s + CMID;

    int tid = threadIdx.x;
    for (int i = tid; i < CIN * CMID; i += MLP_THREADS) {
        int k = i >> 7, j = i & 127;
        W1T[j * S1 + k] = W1[i];
    }
    for (int i = tid; i < CMID * COUT; i += MLP_THREADS) {
        int k = i >> 6, j = i & 63;
        W2T[j * S2 + k] = W2[i];
    }
    if (tid < CMID) b1s[tid] = b1[tid];
    if (tid < COUT) b2s[tid] = b2[tid];

    int warp = tid >> 5, lane = tid & 31;
    int ntiles = NV / TILE_R;

    for (int tile = blockIdx.x; tile < ntiles; tile += gridDim.x) {
        __syncthreads();
        int row0 = tile * TILE_R;
        for (int i = tid; i < TILE_R * CIN / 4; i += MLP_THREADS)
            ((float4*)xs)[i] = ((const float4*)(x + (size_t)row0 * CIN))[i];
        __syncthreads();

        u64 acc[RPW][4];
#pragma unroll
        for (int r = 0; r < RPW; r++)
#pragma unroll
            for (int jj = 0; jj < 4; jj++) acc[r][jj] = 0ull;

        const float* xrow = xs + (warp * RPW) * CIN;
        const float* wbase = W1T + lane * S1;
#pragma unroll 4
        for (int k = 0; k < CIN; k += 2) {
            u64 xv[RPW], wv[4];
#pragma unroll
            for (int r = 0; r < RPW; r++)
                xv[r] = *(const u64*)(xrow + r * CIN + k);
#pragma unroll
            for (int jj = 0; jj < 4; jj++)
                wv[jj] = *(const u64*)(wbase + (jj * 32) * S1 + k);
#pragma unroll
            for (int r = 0; r < RPW; r++)
#pragma unroll
                for (int jj = 0; jj < 4; jj++)
                    acc[r][jj] = fma2(xv[r], wv[jj], acc[r][jj]);
        }
#pragma unroll
        for (int jj = 0; jj < 4; jj++) {
            int j = jj * 32 + lane;
            float b = b1s[j];
#pragma unroll
            for (int r = 0; r < RPW; r++)
                mids[(warp * RPW + r) * CMID + j] = lrelu(sum2(acc[r][jj]) + b);
        }
        __syncwarp();

        u64 acc2[RPW][2];
#pragma unroll
        for (int r = 0; r < RPW; r++) { acc2[r][0] = 0ull; acc2[r][1] = 0ull; }

        const float* mrow = mids + (warp * RPW) * CMID;
        const float* w2base = W2T + lane * S2;
#pragma unroll 4
        for (int k = 0; k < CMID; k += 2) {
            u64 mv[RPW], wv[2];
#pragma unroll
            for (int r = 0; r < RPW; r++)
                mv[r] = *(const u64*)(mrow + r * CMID + k);
#pragma unroll
            for (int jj = 0; jj < 2; jj++)
                wv[jj] = *(const u64*)(w2base + (jj * 32) * S2 + k);
#pragma unroll
            for (int r = 0; r < RPW; r++)
#pragma unroll
                for (int jj = 0; jj < 2; jj++)
                    acc2[r][jj] = fma2(mv[r], wv[jj], acc2[r][jj]);
        }
#pragma unroll
        for (int jj = 0; jj < 2; jj++) {
            int j = jj * 32 + lane;
            float b = b2s[j];
#pragma unroll
            for (int r = 0; r < RPW; r++)
                g_h[(size_t)(row0 + warp * RPW + r) * COUT + j] = sum2(acc2[r][jj]) + b;
        }
    }
}

// ---------------- v2e gather: e_feat[e] = mean over vertices ----------------
// 16 threads per hyperedge, each owns one float4 column.
__global__ void gather_e_kernel() {
    int gt = blockIdx.x * blockDim.x + threadIdx.x;
    int e = gt >> 4;
    if (e >= NE) return;
    int t = gt & 15;
    int base = g_off_e[e], deg = g_cnt_e[e];
    float4 acc = make_float4(0.f, 0.f, 0.f, 0.f);
    for (int j = 0; j < deg; j += 16) {
        int myidx = (j + t < deg) ? __ldg(g_csr_ev + base + j + t) : 0;
        int m = min(16, deg - j);
        for (int jj = 0; jj < m; jj++) {
            int src = __shfl_sync(0xffffffffu, myidx, jj, 16);
            float4 v = __ldg((const float4*)(g_h + (size_t)src * COUT) + t);
            acc.x += v.x; acc.y += v.y; acc.z += v.z; acc.w += v.w;
        }
    }
    float inv = 1.f / (float)max(deg, 1);
    float4 o = make_float4(acc.x * inv, acc.y * inv, acc.z * inv, acc.w * inv);
    ((float4*)(g_efeat + (size_t)e * COUT))[t] = o;
}

// ---------------- fused per-vertex: e2v gather + graph gather + epilogue ----
__global__ void vertex_kernel(const float* __restrict__ w,
                              float* __restrict__ out) {
    int gt = blockIdx.x * blockDim.x + threadIdx.x;
    int v = gt >> 4;
    if (v >= NV) return;
    int t = gt & 15;

    // hypergraph e2v mean over e_feat
    int base_v = g_off_v[v], deg_v = g_cnt_v[v];
    float4 ah = make_float4(0.f, 0.f, 0.f, 0.f);
    for (int j = 0; j < deg_v; j += 16) {
        int myidx = (j + t < deg_v) ? __ldg(g_csr_ve + base_v + j + t) : 0;
        int m = min(16, deg_v - j);
        for (int jj = 0; jj < m; jj++) {
            int src = __shfl_sync(0xffffffffu, myidx, jj, 16);
            float4 e = __ldg((const float4*)(g_efeat + (size_t)src * COUT) + t);
            ah.x += e.x; ah.y += e.y; ah.z += e.z; ah.w += e.w;
        }
    }
    // graph mean over h
    int base_g = g_off_g[v], deg_g = g_cnt_g[v];
    float4 ag = make_float4(0.f, 0.f, 0.f, 0.f);
    for (int j = 0; j < deg_g; j += 16) {
        int myidx = (j + t < deg_g) ? __ldg(g_csr_g + base_g + j + t) : 0;
        int m = min(16, deg_g - j);
        for (int jj = 0; jj < m; jj++) {
            int src = __shfl_sync(0xffffffffu, myidx, jj, 16);
            float4 hv = __ldg((const float4*)(g_h + (size_t)src * COUT) + t);
            ag.x += hv.x; ag.y += hv.y; ag.z += hv.z; ag.w += hv.w;
        }
    }
    float ih = 1.f / (float)max(deg_v, 1);
    float ig = 1.f / (float)max(deg_g, 1);
    float e0 = expf(w[0]), e1 = expf(w[1]);
    float sw0 = e0 / (e0 + e1), sw1 = e1 / (e0 + e1);
    float4 h = __ldg((const float4*)(g_h + (size_t)v * COUT) + t);
    float4 o;
    o.x = lrelu(sw0 * 0.5f * (ag.x * ig + ah.x * ih) + sw1 * h.x);
    o.y = lrelu(sw0 * 0.5f * (ag.y * ig + ah.y * ih) + sw1 * h.y);
    o.z = lrelu(sw0 * 0.5f * (ag.z * ig + ah.z * ih) + sw1 * h.z);
    o.w = lrelu(sw0 * 0.5f * (ag.w * ig + ah.w * ih) + sw1 * h.w);
    ((float4*)(out + (size_t)v * COUT))[t] = o;
}

// ---------------- launch ----------------------------------------------------
extern "C" void kernel_launch(void* const* d_in, const int* in_sizes, int n_in,
                              void* d_out, int out_size) {
    const float* x    = (const float*)d_in[0];
    const float* W1   = (const float*)d_in[1];
    const float* b1   = (const float*)d_in[2];
    const float* W2   = (const float*)d_in[3];
    const float* b2   = (const float*)d_in[4];
    const float* w    = (const float*)d_in[5];
    const int*   hg_v = (const int*)d_in[6];
    const int*   hg_e = (const int*)d_in[7];
    const int*   g_src= (const int*)d_in[8];
    const int*   g_dst= (const int*)d_in[9];
    float* out = (float*)d_out;

    const size_t smem_bytes = (size_t)SMEM_FLOATS * sizeof(float); // ~210KB
    cudaFuncSetAttribute(mlp_kernel, cudaFuncAttributeMaxDynamicSharedMemorySize,
                         (int)smem_bytes);

    // CSR build
    zero_kernel<<<(NV + 255) / 256, 256>>>();
    count_kernel<<<(NP + 255) / 256, 256>>>(hg_v, hg_e, g_dst);
    scan_kernel<<<3, SCAN_T>>>();
    fill_kernel<<<(NP + 255) / 256, 256>>>(hg_v, hg_e, g_src, g_dst);

    // MLP
    mlp_kernel<<<148, MLP_THREADS, smem_bytes>>>(x, W1, b1, W2, b2);

    // gathers
    gather_e_kernel<<<(NE * 16 + 255) / 256, 256>>>();
    vertex_kernel<<<(NV * 16 + 255) / 256, 256>>>(w, out);
}